// round 1
// baseline (speedup 1.0000x reference)
#include <cuda_runtime.h>
#include <math.h>

#define Bc 2
#define Mc 8192
#define Nc (Bc * Mc)
#define KF 16
#define KN 8

// Scratch (device globals: no allocation allowed)
__device__ int g_knn[(size_t)Nc * KF];
__device__ double g_acc[8];

// ---------------- kNN kernel ----------------
// Each block: QPB queries of one cloud, SPLITS threads per query (disjoint
// candidate slices). Whole cloud coords (8192 x float4 = 128KB) staged in
// dynamic SMEM; candidate reads are warp-uniform LDS.128 broadcasts.
#define QPB 128
#define SPLITS 4
#define KTHREADS (QPB * SPLITS)
#define SLICE (Mc / SPLITS)

struct Pair { float d; int i; };

extern "C" __global__ void __launch_bounds__(KTHREADS, 1)
knn_kernel(const float* __restrict__ coords) {
    extern __shared__ unsigned char smem_raw[];
    float4* sh = (float4*)smem_raw;

    const int tid = threadIdx.x;
    const int blocksPerCloud = Mc / QPB;
    const int cloud = blockIdx.x / blocksPerCloud;
    const int qblock = blockIdx.x % blocksPerCloud;

    const float* cb = coords + (size_t)cloud * Mc * 3;
    for (int i = tid; i < Mc; i += KTHREADS)
        sh[i] = make_float4(cb[3 * i], cb[3 * i + 1], cb[3 * i + 2], 0.0f);
    __syncthreads();

    const int qLocal = tid % QPB;     // QPB=128 -> warp-uniform split id
    const int s = tid / QPB;
    const int q = qblock * QPB + qLocal;

    const float4 qc = sh[q];

    // register-resident sorted (ascending) top-16 of this thread's slice
    float dd[KF];
    int ii[KF];
#pragma unroll
    for (int t = 0; t < KF; ++t) { dd[t] = 3.4e38f; ii[t] = 0x7fffffff; }

    const int jb = s * SLICE;
#pragma unroll 4
    for (int j = jb; j < jb + SLICE; ++j) {
        float4 c = sh[j];
        float dx = qc.x - c.x;
        float dy = qc.y - c.y;
        float dz = qc.z - c.z;
        float d2 = fmaf(dz, dz, fmaf(dy, dy, dx * dx));
        if (d2 < dd[KF - 1]) {          // strict <: keeps earlier index on ties
            float v = d2; int vi = j;
#pragma unroll
            for (int t = 0; t < KF; ++t) {
                bool lt = (v < dd[t]);
                float tv = lt ? dd[t] : v;
                int   ti = lt ? ii[t] : vi;
                dd[t] = lt ? v : dd[t];
                ii[t] = lt ? vi : ii[t];
                v = tv; vi = ti;
            }
        }
    }
    __syncthreads();   // done reading coord smem before overwriting with pairs

    Pair* sp = (Pair*)smem_raw;        // 128*4*16*8B = 64KB <= 128KB
    Pair* mine = sp + (qLocal * SPLITS + s) * KF;
#pragma unroll
    for (int t = 0; t < KF; ++t) { mine[t].d = dd[t]; mine[t].i = ii[t]; }
    __syncthreads();

    if (s == 0) {
        const Pair* lp = sp + qLocal * SPLITS * KF;
        int p0 = 0, p1 = 0, p2 = 0, p3 = 0;
        int* out = g_knn + ((size_t)cloud * Mc + q) * KF;
        const int goff = cloud * Mc;
#pragma unroll 1
        for (int r = 0; r < KF; ++r) {
            float d0 = lp[p0].d;          int i0 = lp[p0].i;
            float d1 = lp[KF + p1].d;     int i1 = lp[KF + p1].i;
            float e2 = lp[2 * KF + p2].d; int i2 = lp[2 * KF + p2].i;
            float d3 = lp[3 * KF + p3].d; int i3 = lp[3 * KF + p3].i;
            float da; int ia; int la;
            if (d1 < d0 || (d1 == d0 && i1 < i0)) { da = d1; ia = i1; la = 1; }
            else                                  { da = d0; ia = i0; la = 0; }
            float db; int ib; int lb;
            if (d3 < e2 || (d3 == e2 && i3 < i2)) { db = d3; ib = i3; lb = 3; }
            else                                  { db = e2; ib = i2; lb = 2; }
            int sel; int bi;
            if (db < da || (db == da && ib < ia)) { sel = lb; bi = ib; }
            else                                  { sel = la; bi = ia; }
            out[r] = goff + bi;
            if      (sel == 0) ++p0;
            else if (sel == 1) ++p1;
            else if (sel == 2) ++p2;
            else               ++p3;
        }
    }
}

// ---------------- per-point losses ----------------
__global__ void loss_points_kernel(const float* __restrict__ scores,
                                   const float* __restrict__ coords) {
    const int i = blockIdx.x * blockDim.x + threadIdx.x;
    double num = 0.0, wsum = 0.0, pos = 0.0, neg = 0.0, smooth = 0.0;

    if (i < Nc) {
        const float si = scores[i];
        const float xi = coords[3 * i], yi = coords[3 * i + 1], zi = coords[3 * i + 2];
        float nsum = 0.0f;
        const int* nb = g_knn + (size_t)i * KF;
#pragma unroll
        for (int r = 0; r < KF; ++r) {
            const int n = nb[r];
            const float sn = scores[n];
            const float sd = fabsf(si - sn);
            const float x = (1.0f - sd) / 0.5f;
            const float sig = 1.0f / (1.0f + expf(-x));
            if (r < KN) {
                const float dx = xi - coords[3 * n];
                const float dy = yi - coords[3 * n + 1];
                const float dz = zi - coords[3 * n + 2];
                const float dist = sqrtf(dx * dx + dy * dy + dz * dz);
                const float w = expf(-dist / 0.1f);
                num  += (double)(w * sd * sd);
                wsum += (double)w;
                pos  += (double)logf(sig + 1e-8f);
                nsum += sn;
            } else {
                neg += (double)logf(1.0f - sig + 1e-8f);
            }
        }
        const float dm = si - nsum / 8.0f;
        smooth = (double)(dm * dm);
    }

    __shared__ double red[256];
    double vals[5] = { num, wsum, pos, neg, smooth };
#pragma unroll
    for (int k = 0; k < 5; ++k) {
        red[threadIdx.x] = vals[k];
        __syncthreads();
        for (int off = blockDim.x / 2; off > 0; off >>= 1) {
            if (threadIdx.x < off) red[threadIdx.x] += red[threadIdx.x + off];
            __syncthreads();
        }
        if (threadIdx.x == 0) atomicAdd(&g_acc[k], red[0]);
        __syncthreads();
    }
}

// ---------------- per-cloud sort + dist loss ----------------
__global__ void sort_dist_kernel(const float* __restrict__ scores) {
    __shared__ float ss[Mc];            // 32KB
    const int cloud = blockIdx.x;
    for (int i = threadIdx.x; i < Mc; i += blockDim.x)
        ss[i] = scores[cloud * Mc + i];
    __syncthreads();

    for (int k = 2; k <= Mc; k <<= 1) {
        for (int j = k >> 1; j > 0; j >>= 1) {
            for (int t = threadIdx.x; t < Mc; t += blockDim.x) {
                const int x = t ^ j;
                if (x > t) {
                    const float a = ss[t], b = ss[x];
                    const bool up = ((t & k) == 0);
                    if ((a > b) == up) { ss[t] = b; ss[x] = a; }
                }
            }
            __syncthreads();
        }
    }

    double part = 0.0;
    for (int i = threadIdx.x; i < Mc; i += blockDim.x) {
        const float tgt = (float)i * (1.0f / (float)(Mc - 1));
        const float df = ss[i] - tgt;
        part += (double)(df * df);
    }
    __shared__ double red[1024];
    red[threadIdx.x] = part;
    __syncthreads();
    for (int off = blockDim.x / 2; off > 0; off >>= 1) {
        if (threadIdx.x < off) red[threadIdx.x] += red[threadIdx.x + off];
        __syncthreads();
    }
    if (threadIdx.x == 0) atomicAdd(&g_acc[5], red[0]);
}

// ---------------- zero & finalize ----------------
__global__ void zero_kernel() {
    if (threadIdx.x < 8) g_acc[threadIdx.x] = 0.0;
}

__global__ void finalize_kernel(float* out) {
    const double l_loc = g_acc[0] / fmax(g_acc[1], 1e-8);
    const double l_pos = -g_acc[2] / (double)((size_t)Nc * KN);
    const double l_neg = -g_acc[3] / (double)((size_t)Nc * KN);
    const double l_con = l_pos + l_neg;
    const double l_smooth = g_acc[4] / (double)Nc;
    const double l_dist = g_acc[5] / (double)((size_t)Mc * Bc);
    out[0] = (float)(1.0 * l_loc + 0.5 * l_con + 0.3 * l_dist + 0.2 * l_smooth);
}

extern "C" void kernel_launch(void* const* d_in, const int* in_sizes, int n_in,
                              void* d_out, int out_size) {
    const float* scores = (const float*)d_in[0];
    const float* coords = (const float*)d_in[1];
    // batch_ids (d_in[2]) unused: batches are contiguous blocks of M.

    (void)in_sizes; (void)n_in; (void)out_size;

    cudaFuncSetAttribute(knn_kernel,
                         cudaFuncAttributeMaxDynamicSharedMemorySize,
                         Mc * (int)sizeof(float4));

    zero_kernel<<<1, 32>>>();
    knn_kernel<<<Bc * (Mc / QPB), KTHREADS, Mc * sizeof(float4)>>>(coords);
    loss_points_kernel<<<Nc / 256, 256>>>(scores, coords);
    sort_dist_kernel<<<Bc, 1024>>>(scores);
    finalize_kernel<<<1, 1>>>((float*)d_out);
}